// round 16
// baseline (speedup 1.0000x reference)
#include <cuda_runtime.h>
#include <cuda_bf16.h>
#include <math.h>
#include <cstdint>

// Problem constants
#define BB 16
#define NN 1024
#define DD 256
#define HH 8
#define INF_ 256
#define HID 1024
#define MROWS (BB * NN)   // 16384

// -------- scratch (device globals; no allocation allowed) --------
__device__ float g_h   [MROWS * DD];
__device__ float g_qkv [MROWS * 3 * INF_];
__device__ float g_o   [MROWS * INF_];
__device__ float g_xn  [MROWS * DD];
__device__ float g_h2  [MROWS * DD];
__device__ float g_mid [MROWS * HID];

// ===================== helpers =====================
__device__ __forceinline__ uint32_t smem_u32(const void* p) {
    uint32_t a;
    asm("{ .reg .u64 t; cvta.to.shared.u64 t, %1; cvt.u32.u64 %0, t; }"
        : "=r"(a) : "l"(p));
    return a;
}

#define CP_ASYNC16(dst, src) \
    asm volatile("cp.async.cg.shared.global [%0], [%1], 16;" :: "r"(dst), "l"(src))
#define CP_COMMIT() asm volatile("cp.async.commit_group;" ::: "memory")
#define CP_WAIT(n)  asm volatile("cp.async.wait_group %0;" :: "n"(n) : "memory")

// m16n8k8 tf32 mma (portable at plain sm_103 target)
#define MMA_TF32(c, a, b) \
    asm volatile("mma.sync.aligned.m16n8k8.row.col.f32.tf32.tf32.f32 " \
        "{%0,%1,%2,%3}, {%4,%5,%6,%7}, {%8,%9}, {%0,%1,%2,%3};" \
        : "+f"((c)[0]), "+f"((c)[1]), "+f"((c)[2]), "+f"((c)[3]) \
        : "r"((a)[0]), "r"((a)[1]), "r"((a)[2]), "r"((a)[3]), \
          "r"((b)[0]), "r"((b)[1]))

// ============ LayerNorm: warp-per-row, float4, shfl-only ====================
__global__ __launch_bounds__(256) void ln_kernel(
    const float* __restrict__ x, const float* __restrict__ g,
    const float* __restrict__ b, float* __restrict__ out)
{
    const int w = threadIdx.x >> 5, lane = threadIdx.x & 31;
    const int row = blockIdx.x * 8 + w;
    const float* xp = x + (size_t)row * DD + lane * 8;
    float4 v0 = *(const float4*)(xp);
    float4 v1 = *(const float4*)(xp + 4);
    float s1 = v0.x + v0.y + v0.z + v0.w + v1.x + v1.y + v1.z + v1.w;
    float s2 = v0.x*v0.x + v0.y*v0.y + v0.z*v0.z + v0.w*v0.w
             + v1.x*v1.x + v1.y*v1.y + v1.z*v1.z + v1.w*v1.w;
    #pragma unroll
    for (int o = 16; o; o >>= 1) {
        s1 += __shfl_xor_sync(0xffffffffu, s1, o);
        s2 += __shfl_xor_sync(0xffffffffu, s2, o);
    }
    const float mu  = s1 * (1.0f / DD);
    const float var = s2 * (1.0f / DD) - mu * mu;
    const float inv = rsqrtf(var + 1e-5f);
    const float4 gg0 = *(const float4*)(g + lane * 8);
    const float4 gg1 = *(const float4*)(g + lane * 8 + 4);
    const float4 bb0 = *(const float4*)(b + lane * 8);
    const float4 bb1 = *(const float4*)(b + lane * 8 + 4);
    float4 r0, r1;
    r0.x = (v0.x - mu) * inv * gg0.x + bb0.x;
    r0.y = (v0.y - mu) * inv * gg0.y + bb0.y;
    r0.z = (v0.z - mu) * inv * gg0.z + bb0.z;
    r0.w = (v0.w - mu) * inv * gg0.w + bb0.w;
    r1.x = (v1.x - mu) * inv * gg1.x + bb1.x;
    r1.y = (v1.y - mu) * inv * gg1.y + bb1.y;
    r1.z = (v1.z - mu) * inv * gg1.z + bb1.z;
    r1.w = (v1.w - mu) * inv * gg1.w + bb1.w;
    float* op = out + (size_t)row * DD + lane * 8;
    *(float4*)(op)     = r0;
    *(float4*)(op + 4) = r1;
}

// ============ tf32 mma.sync GEMM + smem-transposed coalesced epilogue =======
// Mainloop = R13 proven config: 128x128 tile, 8 warps 2x4, warp tile 64x32,
// BK=32, 2-stage cp.async, ks-level fragment double buffer, 2 CTAs/SM.
// Epilogue: stage acc through smem (2 half-tile passes) so all global I/O
// is row-linear coalesced instead of 8-way address-divergent.
#define PAD 36
#define GEMM_BUF_FLOATS (128 * PAD)
#define GEMM_DYN_BYTES (4 * GEMM_BUF_FLOATS * 4)
#define EPAD 68

template <bool GELU>
__global__ __launch_bounds__(256, 2) void gemm_mma(
    const float* __restrict__ A, const float* __restrict__ Bm,
    const float* __restrict__ bias,
    const float* __restrict__ res1, const float* __restrict__ res2,
    float* __restrict__ C, int M, int Nn, int K)
{
    extern __shared__ float sm[];
    float* sAbuf = sm;
    float* sBbuf = sm + 2 * GEMM_BUF_FLOATS;

    const int tid = threadIdx.x;
    const int wid = tid >> 5, lane = tid & 31;
    const int bm = blockIdx.y * 128;
    const int bn = blockIdx.x * 128;
    const int wm = (wid >> 2) * 64;
    const int wn = (wid & 3) * 32;

    const int lr = tid >> 1;
    const int lc = (tid & 1) * 16;
    const float* Ag = A  + (size_t)(bm + lr) * K + lc;
    const float* Bg = Bm + (size_t)(bn + lr) * K + lc;
    const uint32_t sAa = smem_u32(sAbuf) + (lr * PAD + lc) * 4;
    const uint32_t sBa = smem_u32(sBbuf) + (lr * PAD + lc) * 4;
    const uint32_t bufBytes = GEMM_BUF_FLOATS * 4;

    float acc[4][4][4];
    #pragma unroll
    for (int mt = 0; mt < 4; mt++)
        #pragma unroll
        for (int nt = 0; nt < 4; nt++)
            #pragma unroll
            for (int q = 0; q < 4; q++) acc[mt][nt][q] = 0.f;

    const int NC = K >> 5;
    {
        #pragma unroll
        for (int i = 0; i < 4; i++) {
            CP_ASYNC16(sAa + i * 16, Ag + i * 4);
            CP_ASYNC16(sBa + i * 16, Bg + i * 4);
        }
        CP_COMMIT();
    }

    const int gr = lane >> 2;
    const int tc = lane & 3;

    for (int cc = 0; cc < NC; cc++) {
        if (cc + 1 < NC) {
            const int nb = (cc + 1) & 1;
            const float* ap = Ag + (cc + 1) * 32;
            const float* bp = Bg + (cc + 1) * 32;
            #pragma unroll
            for (int i = 0; i < 4; i++) {
                CP_ASYNC16(sAa + nb * bufBytes + i * 16, ap + i * 4);
                CP_ASYNC16(sBa + nb * bufBytes + i * 16, bp + i * 4);
            }
            CP_COMMIT();
            CP_WAIT(1);
        } else {
            CP_WAIT(0);
        }
        __syncthreads();

        const float* sA = sAbuf + (cc & 1) * GEMM_BUF_FLOATS;
        const float* sB = sBbuf + (cc & 1) * GEMM_BUF_FLOATS;

        uint32_t bfrag[2][4][2];
        uint32_t afrag[2][4][4];

        #pragma unroll
        for (int nt = 0; nt < 4; nt++) {
            const int n0 = wn + nt * 8 + gr;
            bfrag[0][nt][0] = __float_as_uint(sB[n0 * PAD + tc]);
            bfrag[0][nt][1] = __float_as_uint(sB[n0 * PAD + tc + 4]);
        }
        #pragma unroll
        for (int mt = 0; mt < 4; mt++) {
            const int r = wm + mt * 16 + gr;
            afrag[0][mt][0] = __float_as_uint(sA[r * PAD + tc]);
            afrag[0][mt][1] = __float_as_uint(sA[(r + 8) * PAD + tc]);
            afrag[0][mt][2] = __float_as_uint(sA[r * PAD + tc + 4]);
            afrag[0][mt][3] = __float_as_uint(sA[(r + 8) * PAD + tc + 4]);
        }

        #pragma unroll
        for (int ks = 0; ks < 4; ks++) {
            const int cur = ks & 1, nxt = cur ^ 1;
            if (ks < 3) {
                const int kb = (ks + 1) * 8;
                #pragma unroll
                for (int nt = 0; nt < 4; nt++) {
                    const int n0 = wn + nt * 8 + gr;
                    bfrag[nxt][nt][0] = __float_as_uint(sB[n0 * PAD + kb + tc]);
                    bfrag[nxt][nt][1] = __float_as_uint(sB[n0 * PAD + kb + tc + 4]);
                }
                #pragma unroll
                for (int mt = 0; mt < 4; mt++) {
                    const int r = wm + mt * 16 + gr;
                    afrag[nxt][mt][0] = __float_as_uint(sA[r * PAD + kb + tc]);
                    afrag[nxt][mt][1] = __float_as_uint(sA[(r + 8) * PAD + kb + tc]);
                    afrag[nxt][mt][2] = __float_as_uint(sA[r * PAD + kb + tc + 4]);
                    afrag[nxt][mt][3] = __float_as_uint(sA[(r + 8) * PAD + kb + tc + 4]);
                }
            }
            #pragma unroll
            for (int mt = 0; mt < 4; mt++)
                #pragma unroll
                for (int nt = 0; nt < 4; nt++)
                    MMA_TF32(acc[mt][nt], afrag[cur][mt], bfrag[cur][nt]);
        }
        __syncthreads();
    }

    // ---- epilogue: 2 passes of 64 cols via smem transpose ----
    float* Cst = sm;   // [128][EPAD], 34.8KB, reuses stage memory
    #pragma unroll
    for (int p = 0; p < 2; p++) {
        __syncthreads();   // staging buffer free (mainloop done / pass consumed)
        if (((wid & 3) >> 1) == p) {
            const int cb = wn - p * 64;   // 0 or 32
            #pragma unroll
            for (int mt = 0; mt < 4; mt++)
                #pragma unroll
                for (int nt = 0; nt < 4; nt++)
                    #pragma unroll
                    for (int half = 0; half < 2; half++) {
                        const int r = wm + mt * 16 + gr + half * 8;
                        *(float2*)&Cst[r * EPAD + cb + nt * 8 + 2 * tc] =
                            make_float2(acc[mt][nt][half * 2 + 0],
                                        acc[mt][nt][half * 2 + 1]);
                    }
        }
        __syncthreads();
        // coalesced write: warp wid owns rows wid*16..+16; lane covers 2 cols
        const int colg = bn + p * 64 + lane * 2;
        const float2 bv = bias ? *(const float2*)(bias + colg) : make_float2(0.f, 0.f);
        #pragma unroll 4
        for (int rr = 0; rr < 16; rr++) {
            const int rl = wid * 16 + rr;
            const int row = bm + rl;
            float2 v = *(float2*)&Cst[rl * EPAD + lane * 2];
            v.x += bv.x; v.y += bv.y;
            if (GELU) {
                v.x = 0.5f * v.x * (1.0f + erff(v.x * 0.70710678118654752f));
                v.y = 0.5f * v.y * (1.0f + erff(v.y * 0.70710678118654752f));
            }
            const size_t idx = (size_t)row * Nn + colg;
            if (res1) { float2 r = *(const float2*)(res1 + idx); v.x += r.x; v.y += r.y; }
            if (res2) { float2 r = *(const float2*)(res2 + idx); v.x += r.x; v.y += r.y; }
            *(float2*)(C + idx) = v;
        }
    }
}

// ====== Attention: tensor-core flash, plain tf32 QK and PV ==================
#define PADJ 132
#define PADP 132
#define AQ_OFF 0                        // Qs [128][36]
#define AK_OFF (128 * PAD)              // Ks [128][36]
#define AV_OFF (AK_OFF + 128 * PAD)     // Vt [32][132]
#define AP_OFF (AV_OFF + 32 * PADJ)     // Ps [128][132]
#define ATTN_SMEM_FLOATS (AP_OFF + 128 * PADP)
#define ATTN_DYN_BYTES   (ATTN_SMEM_FLOATS * 4)

__global__ __launch_bounds__(256) void attn_kernel(
    const float* __restrict__ qkv, float* __restrict__ o)
{
    extern __shared__ float sm[];
    float* Qs = sm + AQ_OFF;
    float* Ks = sm + AK_OFF;
    float* Vt = sm + AV_OFF;
    float* Ps = sm + AP_OFF;

    const int tid = threadIdx.x;
    const int b = blockIdx.y >> 3, h = blockIdx.y & 7;
    const int q0 = blockIdx.x * 128;
    const int w = tid >> 5, lane = tid & 31;
    const int gr = lane >> 2, tc = lane & 3;
    const int qm = w * 16;
    const int par = tid & 1;
    const float scale = 0.17677669529663687f; // 1/sqrt(32)

    {
        const int rr = tid >> 1, cb = par * 16;
        const float* qp = qkv + ((size_t)(b * NN + q0 + rr) * 768) + h * 32 + cb;
        #pragma unroll
        for (int i = 0; i < 16; i += 4) {
            float4 v = *(const float4*)(qp + i);
            Qs[rr * PAD + cb + i + 0] = v.x * scale;
            Qs[rr * PAD + cb + i + 1] = v.y * scale;
            Qs[rr * PAD + cb + i + 2] = v.z * scale;
            Qs[rr * PAD + cb + i + 3] = v.w * scale;
        }
    }

    float oa[4][4];
    #pragma unroll
    for (int nf = 0; nf < 4; nf++)
        #pragma unroll
        for (int q = 0; q < 4; q++) oa[nf][q] = 0.f;
    float m0 = -1e30f, m1 = -1e30f, l0 = 0.f, l1 = 0.f;

    for (int kt = 0; kt < NN / 128; kt++) {
        const int k0 = kt * 128;
        __syncthreads();
        {
            const int rr = tid >> 1, cb = par * 16;
            const float* kp = qkv + ((size_t)(b * NN + k0 + rr) * 768) + 256 + h * 32 + cb;
            const float* vp = kp + 256;
            float vv[16];
            #pragma unroll
            for (int i = 0; i < 16; i += 4) {
                float4 kv = *(const float4*)(kp + i);
                Ks[rr * PAD + cb + i + 0] = kv.x;
                Ks[rr * PAD + cb + i + 1] = kv.y;
                Ks[rr * PAD + cb + i + 2] = kv.z;
                Ks[rr * PAD + cb + i + 3] = kv.w;
                float4 vq = *(const float4*)(vp + i);
                vv[i + 0] = vq.x; vv[i + 1] = vq.y; vv[i + 2] = vq.z; vv[i + 3] = vq.w;
            }
            #pragma unroll
            for (int ii = 0; ii < 16; ii++) {
                int i = (ii + par) & 15;
                Vt[(cb + i) * PADJ + rr] = vv[i];
            }
        }
        __syncthreads();

        float sc[16][4];
        #pragma unroll
        for (int nf = 0; nf < 16; nf++)
            #pragma unroll
            for (int q = 0; q < 4; q++) sc[nf][q] = 0.f;
        #pragma unroll
        for (int ks = 0; ks < 4; ks++) {
            const int kb = ks * 8;
            uint32_t afrag[4];
            afrag[0] = __float_as_uint(Qs[(qm + gr) * PAD + kb + tc]);
            afrag[1] = __float_as_uint(Qs[(qm + gr + 8) * PAD + kb + tc]);
            afrag[2] = __float_as_uint(Qs[(qm + gr) * PAD + kb + tc + 4]);
            afrag[3] = __float_as_uint(Qs[(qm + gr + 8) * PAD + kb + tc + 4]);
            #pragma unroll
            for (int nf = 0; nf < 16; nf++) {
                uint32_t bfrag[2];
                bfrag[0] = __float_as_uint(Ks[(nf * 8 + gr) * PAD + kb + tc]);
                bfrag[1] = __float_as_uint(Ks[(nf * 8 + gr) * PAD + kb + tc + 4]);
                MMA_TF32(sc[nf], afrag, bfrag);
            }
        }

        float tm0 = -1e30f, tm1 = -1e30f;
        #pragma unroll
        for (int nf = 0; nf < 16; nf++) {
            tm0 = fmaxf(tm0, fmaxf(sc[nf][0], sc[nf][1]));
            tm1 = fmaxf(tm1, fmaxf(sc[nf][2], sc[nf][3]));
        }
        tm0 = fmaxf(tm0, __shfl_xor_sync(0xffffffffu, tm0, 1));
        tm0 = fmaxf(tm0, __shfl_xor_sync(0xffffffffu, tm0, 2));
        tm1 = fmaxf(tm1, __shfl_xor_sync(0xffffffffu, tm1, 1));
        tm1 = fmaxf(tm1, __shfl_xor_sync(0xffffffffu, tm1, 2));
        float mn0 = fmaxf(m0, tm0), mn1 = fmaxf(m1, tm1);
        float corr0 = __expf(m0 - mn0), corr1 = __expf(m1 - mn1);
        m0 = mn0; m1 = mn1;
        float ls0 = 0.f, ls1 = 0.f;
        #pragma unroll
        for (int nf = 0; nf < 16; nf++) {
            float p0 = __expf(sc[nf][0] - mn0);
            float p1 = __expf(sc[nf][1] - mn0);
            float p2 = __expf(sc[nf][2] - mn1);
            float p3 = __expf(sc[nf][3] - mn1);
            ls0 += p0 + p1; ls1 += p2 + p3;
            *(float2*)(Ps + (qm + gr) * PADP + nf * 8 + 2 * tc)     = make_float2(p0, p1);
            *(float2*)(Ps + (qm + gr + 8) * PADP + nf * 8 + 2 * tc) = make_float2(p2, p3);
        }
        ls0 += __shfl_xor_sync(0xffffffffu, ls0, 1);
        ls0 += __shfl_xor_sync(0xffffffffu, ls0, 2);
        ls1 += __shfl_xor_sync(0xffffffffu, ls1, 1);
        ls1 += __shfl_xor_sync(0xffffffffu, ls1, 2);
        l0 = l0 * corr0 + ls0;
        l1 = l1 * corr1 + ls1;
        #pragma unroll
        for (int nf = 0; nf < 4; nf++) {
            oa[nf][0] *= corr0; oa[nf][1] *= corr0;
            oa[nf][2] *= corr1; oa[nf][3] *= corr1;
        }
        __syncwarp();

        #pragma unroll
        for (int ksj = 0; ksj < 16; ksj++) {
            const int j = ksj * 8;
            uint32_t afrag[4];
            afrag[0] = __float_as_uint(Ps[(qm + gr) * PADP + j + tc]);
            afrag[1] = __float_as_uint(Ps[(qm + gr + 8) * PADP + j + tc]);
            afrag[2] = __float_as_uint(Ps[(qm + gr) * PADP + j + tc + 4]);
            afrag[3] = __float_as_uint(Ps[(qm + gr + 8) * PADP + j + tc + 4]);
            #pragma unroll
            for (int nf = 0; nf < 4; nf++) {
                uint32_t bfrag[2];
                bfrag[0] = __float_as_uint(Vt[(nf * 8 + gr) * PADJ + j + tc]);
                bfrag[1] = __float_as_uint(Vt[(nf * 8 + gr) * PADJ + j + tc + 4]);
                MMA_TF32(oa[nf], afrag, bfrag);
            }
        }
    }

    const float inv0 = 1.0f / l0, inv1 = 1.0f / l1;
    const int r0 = q0 + qm + gr, r1 = r0 + 8;
    float* ob = o + (size_t)(b * NN) * 256 + h * 32;
    #pragma unroll
    for (int nf = 0; nf < 4; nf++) {
        const int d = nf * 8 + 2 * tc;
        *(float2*)(ob + (size_t)r0 * 256 + d) = make_float2(oa[nf][0] * inv0, oa[nf][1] * inv0);
        *(float2*)(ob + (size_t)r1 * 256 + d) = make_float2(oa[nf][2] * inv1, oa[nf][3] * inv1);
    }
}

// ================================ launch ====================================
extern "C" void kernel_launch(void* const* d_in, const int* in_sizes, int n_in,
                              void* d_out, int out_size)
{
    const float* x     = (const float*)d_in[0];
    const float* g1    = (const float*)d_in[2];
    const float* b1    = (const float*)d_in[3];
    const float* Wqkv  = (const float*)d_in[4];
    const float* Wproj = (const float*)d_in[5];
    const float* bproj = (const float*)d_in[6];
    const float* g2    = (const float*)d_in[7];
    const float* b2    = (const float*)d_in[8];
    const float* W1    = (const float*)d_in[9];
    const float* bb1   = (const float*)d_in[10];
    const float* W2    = (const float*)d_in[11];
    const float* bb2   = (const float*)d_in[12];
    float* out = (float*)d_out;

    float *p_h, *p_qkv, *p_o, *p_xn, *p_h2, *p_mid;
    cudaGetSymbolAddress((void**)&p_h,   g_h);
    cudaGetSymbolAddress((void**)&p_qkv, g_qkv);
    cudaGetSymbolAddress((void**)&p_o,   g_o);
    cudaGetSymbolAddress((void**)&p_xn,  g_xn);
    cudaGetSymbolAddress((void**)&p_h2,  g_h2);
    cudaGetSymbolAddress((void**)&p_mid, g_mid);

    cudaFuncSetAttribute(gemm_mma<false>, cudaFuncAttributeMaxDynamicSharedMemorySize, GEMM_DYN_BYTES);
    cudaFuncSetAttribute(gemm_mma<true>,  cudaFuncAttributeMaxDynamicSharedMemorySize, GEMM_DYN_BYTES);
    cudaFuncSetAttribute(attn_kernel,     cudaFuncAttributeMaxDynamicSharedMemorySize, ATTN_DYN_BYTES);

    // 1) h = LN1(x)
    ln_kernel<<<MROWS / 8, 256>>>(x, g1, b1, p_h);

    // 2) qkv = h @ Wqkv^T
    gemm_mma<false><<<dim3(768 / 128, MROWS / 128), 256, GEMM_DYN_BYTES>>>(
        p_h, Wqkv, nullptr, nullptr, nullptr, p_qkv, MROWS, 3 * INF_, DD);

    // 3) attention -> o
    attn_kernel<<<dim3(NN / 128, BB * HH), 256, ATTN_DYN_BYTES>>>(p_qkv, p_o);

    // 4) xn = x + (o @ Wproj^T + bproj + h)
    gemm_mma<false><<<dim3(INF_ / 128, MROWS / 128), 256, GEMM_DYN_BYTES>>>(
        p_o, Wproj, bproj, p_h, x, p_xn, MROWS, INF_, INF_);

    // 5) h2 = LN2(xn)
    ln_kernel<<<MROWS / 8, 256>>>(p_xn, g2, b2, p_h2);

    // 6) mid = gelu(h2 @ W1^T + bb1)
    gemm_mma<true><<<dim3(HID / 128, MROWS / 128), 256, GEMM_DYN_BYTES>>>(
        p_h2, W1, bb1, nullptr, nullptr, p_mid, MROWS, HID, DD);

    // 7) out = xn + mid @ W2^T + bb2
    gemm_mma<false><<<dim3(DD / 128, MROWS / 128), 256, GEMM_DYN_BYTES>>>(
        p_mid, W2, bb2, p_xn, nullptr, out, MROWS, DD, HID);
}

// round 17
// speedup vs baseline: 1.2829x; 1.2829x over previous
#include <cuda_runtime.h>
#include <cuda_bf16.h>
#include <math.h>
#include <cstdint>

// Problem constants
#define BB 16
#define NN 1024
#define DD 256
#define HH 8
#define INF_ 256
#define HID 1024
#define MROWS (BB * NN)   // 16384

// -------- scratch (device globals; no allocation allowed) --------
__device__ float g_h   [MROWS * DD];
__device__ float g_qkv [MROWS * 3 * INF_];
__device__ float g_o   [MROWS * INF_];
__device__ float g_xn  [MROWS * DD];
__device__ float g_mid_dummy[1];
__device__ __nv_bfloat16 g_hb  [MROWS * DD];
__device__ __nv_bfloat16 g_h2b [MROWS * DD];
__device__ __nv_bfloat16 g_midb[MROWS * HID];
__device__ __nv_bfloat16 g_Wqkvb[768 * DD];
__device__ __nv_bfloat16 g_W1b  [HID * DD];
__device__ __nv_bfloat16 g_W2b  [DD * HID];

// ===================== helpers =====================
__device__ __forceinline__ uint32_t smem_u32(const void* p) {
    uint32_t a;
    asm("{ .reg .u64 t; cvta.to.shared.u64 t, %1; cvt.u32.u64 %0, t; }"
        : "=r"(a) : "l"(p));
    return a;
}

#define CP_ASYNC16(dst, src) \
    asm volatile("cp.async.cg.shared.global [%0], [%1], 16;" :: "r"(dst), "l"(src))
#define CP_COMMIT() asm volatile("cp.async.commit_group;" ::: "memory")
#define CP_WAIT(n)  asm volatile("cp.async.wait_group %0;" :: "n"(n) : "memory")

#define MMA_TF32(c, a, b) \
    asm volatile("mma.sync.aligned.m16n8k8.row.col.f32.tf32.tf32.f32 " \
        "{%0,%1,%2,%3}, {%4,%5,%6,%7}, {%8,%9}, {%0,%1,%2,%3};" \
        : "+f"((c)[0]), "+f"((c)[1]), "+f"((c)[2]), "+f"((c)[3]) \
        : "r"((a)[0]), "r"((a)[1]), "r"((a)[2]), "r"((a)[3]), \
          "r"((b)[0]), "r"((b)[1]))

#define MMA_BF16(c, a, b) \
    asm volatile("mma.sync.aligned.m16n8k16.row.col.f32.bf16.bf16.f32 " \
        "{%0,%1,%2,%3}, {%4,%5,%6,%7}, {%8,%9}, {%0,%1,%2,%3};" \
        : "+f"((c)[0]), "+f"((c)[1]), "+f"((c)[2]), "+f"((c)[3]) \
        : "r"((a)[0]), "r"((a)[1]), "r"((a)[2]), "r"((a)[3]), \
          "r"((b)[0]), "r"((b)[1]))

// ============ weight fp32 -> bf16 conversion (one launch) ===================
__global__ __launch_bounds__(256) void cvt_weights(
    const float* __restrict__ wqkv, const float* __restrict__ w1,
    const float* __restrict__ w2,
    __nv_bfloat16* __restrict__ dq, __nv_bfloat16* __restrict__ d1,
    __nv_bfloat16* __restrict__ d2)
{
    const int n0 = 768 * DD, n1 = HID * DD, n2 = DD * HID;
    for (int i = blockIdx.x * 256 + threadIdx.x; i < n0 + n1 + n2;
         i += gridDim.x * 256) {
        if (i < n0) dq[i] = __float2bfloat16_rn(wqkv[i]);
        else if (i < n0 + n1) d1[i - n0] = __float2bfloat16_rn(w1[i - n0]);
        else d2[i - n0 - n1] = __float2bfloat16_rn(w2[i - n0 - n1]);
    }
}

// ============ LayerNorm: warp-per-row; writes bf16 (+ optional fp32) ========
template <bool DUAL>
__global__ __launch_bounds__(256) void ln_kernel(
    const float* __restrict__ x, const float* __restrict__ g,
    const float* __restrict__ b, float* __restrict__ outf,
    __nv_bfloat16* __restrict__ outb)
{
    const int w = threadIdx.x >> 5, lane = threadIdx.x & 31;
    const int row = blockIdx.x * 8 + w;
    const float* xp = x + (size_t)row * DD + lane * 8;
    float4 v0 = *(const float4*)(xp);
    float4 v1 = *(const float4*)(xp + 4);
    float s1 = v0.x + v0.y + v0.z + v0.w + v1.x + v1.y + v1.z + v1.w;
    float s2 = v0.x*v0.x + v0.y*v0.y + v0.z*v0.z + v0.w*v0.w
             + v1.x*v1.x + v1.y*v1.y + v1.z*v1.z + v1.w*v1.w;
    #pragma unroll
    for (int o = 16; o; o >>= 1) {
        s1 += __shfl_xor_sync(0xffffffffu, s1, o);
        s2 += __shfl_xor_sync(0xffffffffu, s2, o);
    }
    const float mu  = s1 * (1.0f / DD);
    const float var = s2 * (1.0f / DD) - mu * mu;
    const float inv = rsqrtf(var + 1e-5f);
    const float4 gg0 = *(const float4*)(g + lane * 8);
    const float4 gg1 = *(const float4*)(g + lane * 8 + 4);
    const float4 bb0 = *(const float4*)(b + lane * 8);
    const float4 bb1 = *(const float4*)(b + lane * 8 + 4);
    float r[8];
    r[0] = (v0.x - mu) * inv * gg0.x + bb0.x;
    r[1] = (v0.y - mu) * inv * gg0.y + bb0.y;
    r[2] = (v0.z - mu) * inv * gg0.z + bb0.z;
    r[3] = (v0.w - mu) * inv * gg0.w + bb0.w;
    r[4] = (v1.x - mu) * inv * gg1.x + bb1.x;
    r[5] = (v1.y - mu) * inv * gg1.y + bb1.y;
    r[6] = (v1.z - mu) * inv * gg1.z + bb1.z;
    r[7] = (v1.w - mu) * inv * gg1.w + bb1.w;
    if (DUAL) {
        float* op = outf + (size_t)row * DD + lane * 8;
        *(float4*)(op)     = make_float4(r[0], r[1], r[2], r[3]);
        *(float4*)(op + 4) = make_float4(r[4], r[5], r[6], r[7]);
    }
    __nv_bfloat162* ob = (__nv_bfloat162*)(outb + (size_t)row * DD + lane * 8);
    #pragma unroll
    for (int i = 0; i < 4; i++)
        ob[i] = __floats2bfloat162_rn(r[2 * i], r[2 * i + 1]);
}

// ============ tf32 GEMM (proj only) + coalesced epilogue ====================
#define PAD 36
#define GEMM_BUF_FLOATS (128 * PAD)
#define GEMM_DYN_BYTES (4 * GEMM_BUF_FLOATS * 4)
#define EPAD 68

template <bool GELU>
__global__ __launch_bounds__(256, 2) void gemm_mma(
    const float* __restrict__ A, const float* __restrict__ Bm,
    const float* __restrict__ bias,
    const float* __restrict__ res1, const float* __restrict__ res2,
    float* __restrict__ C, int M, int Nn, int K)
{
    extern __shared__ float sm[];
    float* sAbuf = sm;
    float* sBbuf = sm + 2 * GEMM_BUF_FLOATS;

    const int tid = threadIdx.x;
    const int wid = tid >> 5, lane = tid & 31;
    const int bm = blockIdx.y * 128;
    const int bn = blockIdx.x * 128;
    const int wm = (wid >> 2) * 64;
    const int wn = (wid & 3) * 32;

    const int lr = tid >> 1;
    const int lc = (tid & 1) * 16;
    const float* Ag = A  + (size_t)(bm + lr) * K + lc;
    const float* Bg = Bm + (size_t)(bn + lr) * K + lc;
    const uint32_t sAa = smem_u32(sAbuf) + (lr * PAD + lc) * 4;
    const uint32_t sBa = smem_u32(sBbuf) + (lr * PAD + lc) * 4;
    const uint32_t bufBytes = GEMM_BUF_FLOATS * 4;

    float acc[4][4][4];
    #pragma unroll
    for (int mt = 0; mt < 4; mt++)
        #pragma unroll
        for (int nt = 0; nt < 4; nt++)
            #pragma unroll
            for (int q = 0; q < 4; q++) acc[mt][nt][q] = 0.f;

    const int NC = K >> 5;
    {
        #pragma unroll
        for (int i = 0; i < 4; i++) {
            CP_ASYNC16(sAa + i * 16, Ag + i * 4);
            CP_ASYNC16(sBa + i * 16, Bg + i * 4);
        }
        CP_COMMIT();
    }

    const int gr = lane >> 2;
    const int tc = lane & 3;

    for (int cc = 0; cc < NC; cc++) {
        if (cc + 1 < NC) {
            const int nb = (cc + 1) & 1;
            const float* ap = Ag + (cc + 1) * 32;
            const float* bp = Bg + (cc + 1) * 32;
            #pragma unroll
            for (int i = 0; i < 4; i++) {
                CP_ASYNC16(sAa + nb * bufBytes + i * 16, ap + i * 4);
                CP_ASYNC16(sBa + nb * bufBytes + i * 16, bp + i * 4);
            }
            CP_COMMIT();
            CP_WAIT(1);
        } else {
            CP_WAIT(0);
        }
        __syncthreads();

        const float* sA = sAbuf + (cc & 1) * GEMM_BUF_FLOATS;
        const float* sB = sBbuf + (cc & 1) * GEMM_BUF_FLOATS;

        uint32_t bfrag[2][4][2];
        uint32_t afrag[2][4][4];
        #pragma unroll
        for (int nt = 0; nt < 4; nt++) {
            const int n0 = wn + nt * 8 + gr;
            bfrag[0][nt][0] = __float_as_uint(sB[n0 * PAD + tc]);
            bfrag[0][nt][1] = __float_as_uint(sB[n0 * PAD + tc + 4]);
        }
        #pragma unroll
        for (int mt = 0; mt < 4; mt++) {
            const int r = wm + mt * 16 + gr;
            afrag[0][mt][0] = __float_as_uint(sA[r * PAD + tc]);
            afrag[0][mt][1] = __float_as_uint(sA[(r + 8) * PAD + tc]);
            afrag[0][mt][2] = __float_as_uint(sA[r * PAD + tc + 4]);
            afrag[0][mt][3] = __float_as_uint(sA[(r + 8) * PAD + tc + 4]);
        }

        #pragma unroll
        for (int ks = 0; ks < 4; ks++) {
            const int cur = ks & 1, nxt = cur ^ 1;
            if (ks < 3) {
                const int kb = (ks + 1) * 8;
                #pragma unroll
                for (int nt = 0; nt < 4; nt++) {
                    const int n0 = wn + nt * 8 + gr;
                    bfrag[nxt][nt][0] = __float_as_uint(sB[n0 * PAD + kb + tc]);
                    bfrag[nxt][nt][1] = __float_as_uint(sB[n0 * PAD + kb + tc + 4]);
                }
                #pragma unroll
                for (int mt = 0; mt < 4; mt++) {
                    const int r = wm + mt * 16 + gr;
                    afrag[nxt][mt][0] = __float_as_uint(sA[r * PAD + kb + tc]);
                    afrag[nxt][mt][1] = __float_as_uint(sA[(r + 8) * PAD + kb + tc]);
                    afrag[nxt][mt][2] = __float_as_uint(sA[r * PAD + kb + tc + 4]);
                    afrag[nxt][mt][3] = __float_as_uint(sA[(r + 8) * PAD + kb + tc + 4]);
                }
            }
            #pragma unroll
            for (int mt = 0; mt < 4; mt++)
                #pragma unroll
                for (int nt = 0; nt < 4; nt++)
                    MMA_TF32(acc[mt][nt], afrag[cur][mt], bfrag[cur][nt]);
        }
        __syncthreads();
    }

    float* Cst = sm;
    #pragma unroll
    for (int p = 0; p < 2; p++) {
        __syncthreads();
        if (((wid & 3) >> 1) == p) {
            const int cb = wn - p * 64;
            #pragma unroll
            for (int mt = 0; mt < 4; mt++)
                #pragma unroll
                for (int nt = 0; nt < 4; nt++)
                    #pragma unroll
                    for (int half = 0; half < 2; half++) {
                        const int r = wm + mt * 16 + gr + half * 8;
                        *(float2*)&Cst[r * EPAD + cb + nt * 8 + 2 * tc] =
                            make_float2(acc[mt][nt][half * 2 + 0],
                                        acc[mt][nt][half * 2 + 1]);
                    }
        }
        __syncthreads();
        const int colg = bn + p * 64 + lane * 2;
        const float2 bv = bias ? *(const float2*)(bias + colg) : make_float2(0.f, 0.f);
        #pragma unroll 4
        for (int rr = 0; rr < 16; rr++) {
            const int rl = wid * 16 + rr;
            const int row = bm + rl;
            float2 v = *(float2*)&Cst[rl * EPAD + lane * 2];
            v.x += bv.x; v.y += bv.y;
            if (GELU) {
                v.x = 0.5f * v.x * (1.0f + erff(v.x * 0.70710678118654752f));
                v.y = 0.5f * v.y * (1.0f + erff(v.y * 0.70710678118654752f));
            }
            const size_t idx = (size_t)row * Nn + colg;
            if (res1) { float2 r = *(const float2*)(res1 + idx); v.x += r.x; v.y += r.y; }
            if (res2) { float2 r = *(const float2*)(res2 + idx); v.x += r.x; v.y += r.y; }
            *(float2*)(C + idx) = v;
        }
    }
}

// ============ bf16 m16n8k16 GEMM: C = A@B^T + epilogue ======================
// 128x128 tile, 8 warps 2x4, warp tile 64x32, BK=64 halfs (=128B/row),
// 2-stage cp.async, frag double buffer. Word stride 36 (=72-half rows):
// identical conflict-free bank pattern as the fp32 PAD-36 layout.
#define BWRD 36                     // words per row
#define BMATW (128 * BWRD)          // words per matrix per stage
#define BSTGW (2 * BMATW)           // words per stage (A+B)
#define GEMM_BF_BYTES (2 * BSTGW * 4)   // 73728 B

template <bool GELU, bool OUTBF>
__global__ __launch_bounds__(256, 2) void gemm_bf16(
    const __nv_bfloat16* __restrict__ A, const __nv_bfloat16* __restrict__ Bm,
    const float* __restrict__ bias, const float* __restrict__ res1,
    void* __restrict__ Cv, int M, int Nn, int K)
{
    extern __shared__ float sm[];
    uint32_t* smw = (uint32_t*)sm;

    const int tid = threadIdx.x;
    const int wid = tid >> 5, lane = tid & 31;
    const int bm = blockIdx.y * 128;
    const int bn = blockIdx.x * 128;
    const int wm = (wid >> 2) * 64;
    const int wn = (wid & 3) * 32;

    const int lr = tid >> 1;
    const int lch = (tid & 1) * 32;           // half offset within row
    const __nv_bfloat16* Ag = A  + (size_t)(bm + lr) * K + lch;
    const __nv_bfloat16* Bg = Bm + (size_t)(bn + lr) * K + lch;
    const uint32_t sBase = smem_u32(sm);
    const uint32_t sAoff = (lr * BWRD + (tid & 1) * 16) * 4;
    const uint32_t sBoff = (BMATW + lr * BWRD + (tid & 1) * 16) * 4;
    const uint32_t stageBytes = BSTGW * 4;

    float acc[4][4][4];
    #pragma unroll
    for (int mt = 0; mt < 4; mt++)
        #pragma unroll
        for (int nt = 0; nt < 4; nt++)
            #pragma unroll
            for (int q = 0; q < 4; q++) acc[mt][nt][q] = 0.f;

    const int NC = K >> 6;   // chunks of 64 halfs
    {
        #pragma unroll
        for (int i = 0; i < 4; i++) {
            CP_ASYNC16(sBase + sAoff + i * 16, Ag + i * 8);
            CP_ASYNC16(sBase + sBoff + i * 16, Bg + i * 8);
        }
        CP_COMMIT();
    }

    const int gr = lane >> 2;
    const int tc = lane & 3;

    for (int cc = 0; cc < NC; cc++) {
        if (cc + 1 < NC) {
            const uint32_t sb = sBase + ((cc + 1) & 1) * stageBytes;
            const __nv_bfloat16* ap = Ag + (cc + 1) * 64;
            const __nv_bfloat16* bp = Bg + (cc + 1) * 64;
            #pragma unroll
            for (int i = 0; i < 4; i++) {
                CP_ASYNC16(sb + sAoff + i * 16, ap + i * 8);
                CP_ASYNC16(sb + sBoff + i * 16, bp + i * 8);
            }
            CP_COMMIT();
            CP_WAIT(1);
        } else {
            CP_WAIT(0);
        }
        __syncthreads();

        const uint32_t* sA = smw + (cc & 1) * BSTGW;
        const uint32_t* sB = sA + BMATW;

        uint32_t bfrag[2][4][2];
        uint32_t afrag[2][4][4];
        #pragma unroll
        for (int nt = 0; nt < 4; nt++) {
            const int n0 = wn + nt * 8 + gr;
            bfrag[0][nt][0] = sB[n0 * BWRD + tc];
            bfrag[0][nt][1] = sB[n0 * BWRD + tc + 4];
        }
        #pragma unroll
        for (int mt = 0; mt < 4; mt++) {
            const int r = wm + mt * 16 + gr;
            afrag[0][mt][0] = sA[r * BWRD + tc];
            afrag[0][mt][1] = sA[(r + 8) * BWRD + tc];
            afrag[0][mt][2] = sA[r * BWRD + tc + 4];
            afrag[0][mt][3] = sA[(r + 8) * BWRD + tc + 4];
        }

        #pragma unroll
        for (int ks = 0; ks < 4; ks++) {   // k16 steps; kb = ks*8 words
            const int cur = ks & 1, nxt = cur ^ 1;
            if (ks < 3) {
                const int kb = (ks + 1) * 8;
                #pragma unroll
                for (int nt = 0; nt < 4; nt++) {
                    const int n0 = wn + nt * 8 + gr;
                    bfrag[nxt][nt][0] = sB[n0 * BWRD + kb + tc];
                    bfrag[nxt][nt][1] = sB[n0 * BWRD + kb + tc + 4];
                }
                #pragma unroll
                for (int mt = 0; mt < 4; mt++) {
                    const int r = wm + mt * 16 + gr;
                    afrag[nxt][mt][0] = sA[r * BWRD + kb + tc];
                    afrag[nxt][mt][1] = sA[(r + 8) * BWRD + kb + tc];
                    afrag[nxt][mt][2] = sA[r * BWRD + kb + tc + 4];
                    afrag[nxt][mt][3] = sA[(r + 8) * BWRD + kb + tc + 4];
                }
            }
            #pragma unroll
            for (int mt = 0; mt < 4; mt++)
                #pragma unroll
                for (int nt = 0; nt < 4; nt++)
                    MMA_BF16(acc[mt][nt], afrag[cur][mt], bfrag[cur][nt]);
        }
        __syncthreads();
    }

    // coalesced epilogue via smem transpose
    float* Cst = sm;
    #pragma unroll
    for (int p = 0; p < 2; p++) {
        __syncthreads();
        if (((wid & 3) >> 1) == p) {
            const int cb = wn - p * 64;
            #pragma unroll
            for (int mt = 0; mt < 4; mt++)
                #pragma unroll
                for (int nt = 0; nt < 4; nt++)
                    #pragma unroll
                    for (int half = 0; half < 2; half++) {
                        const int r = wm + mt * 16 + gr + half * 8;
                        *(float2*)&Cst[r * EPAD + cb + nt * 8 + 2 * tc] =
                            make_float2(acc[mt][nt][half * 2 + 0],
                                        acc[mt][nt][half * 2 + 1]);
                    }
        }
        __syncthreads();
        const int colg = bn + p * 64 + lane * 2;
        const float2 bv = bias ? *(const float2*)(bias + colg) : make_float2(0.f, 0.f);
        #pragma unroll 4
        for (int rr = 0; rr < 16; rr++) {
            const int rl = wid * 16 + rr;
            const int row = bm + rl;
            float2 v = *(float2*)&Cst[rl * EPAD + lane * 2];
            v.x += bv.x; v.y += bv.y;
            if (GELU) {
                v.x = 0.5f * v.x * (1.0f + erff(v.x * 0.70710678118654752f));
                v.y = 0.5f * v.y * (1.0f + erff(v.y * 0.70710678118654752f));
            }
            const size_t idx = (size_t)row * Nn + colg;
            if (res1) { float2 r = *(const float2*)(res1 + idx); v.x += r.x; v.y += r.y; }
            if (OUTBF) {
                *(__nv_bfloat162*)((__nv_bfloat16*)Cv + idx) =
                    __floats2bfloat162_rn(v.x, v.y);
            } else {
                *(float2*)((float*)Cv + idx) = v;
            }
        }
    }
}

// ====== Attention: tensor-core flash, plain tf32 QK and PV ==================
#define PADJ 132
#define PADP 132
#define AQ_OFF 0
#define AK_OFF (128 * PAD)
#define AV_OFF (AK_OFF + 128 * PAD)
#define AP_OFF (AV_OFF + 32 * PADJ)
#define ATTN_SMEM_FLOATS (AP_OFF + 128 * PADP)
#define ATTN_DYN_BYTES   (ATTN_SMEM_FLOATS * 4)

__global__ __launch_bounds__(256) void attn_kernel(
    const float* __restrict__ qkv, float* __restrict__ o)
{
    extern __shared__ float sm[];
    float* Qs = sm + AQ_OFF;
    float* Ks = sm + AK_OFF;
    float* Vt = sm + AV_OFF;
    float* Ps = sm + AP_OFF;

    const int tid = threadIdx.x;
    const int b = blockIdx.y >> 3, h = blockIdx.y & 7;
    const int q0 = blockIdx.x * 128;
    const int w = tid >> 5, lane = tid & 31;
    const int gr = lane >> 2, tc = lane & 3;
    const int qm = w * 16;
    const int par = tid & 1;
    const float scale = 0.17677669529663687f;

    {
        const int rr = tid >> 1, cb = par * 16;
        const float* qp = qkv + ((size_t)(b * NN + q0 + rr) * 768) + h * 32 + cb;
        #pragma unroll
        for (int i = 0; i < 16; i += 4) {
            float4 v = *(const float4*)(qp + i);
            Qs[rr * PAD + cb + i + 0] = v.x * scale;
            Qs[rr * PAD + cb + i + 1] = v.y * scale;
            Qs[rr * PAD + cb + i + 2] = v.z * scale;
            Qs[rr * PAD + cb + i + 3] = v.w * scale;
        }
    }

    float oa[4][4];
    #pragma unroll
    for (int nf = 0; nf < 4; nf++)
        #pragma unroll
        for (int q = 0; q < 4; q++) oa[nf][q] = 0.f;
    float m0 = -1e30f, m1 = -1e30f, l0 = 0.f, l1 = 0.f;

    for (int kt = 0; kt < NN / 128; kt++) {
        const int k0 = kt * 128;
        __syncthreads();
        {
            const int rr = tid >> 1, cb = par * 16;
            const float* kp = qkv + ((size_t)(b * NN + k0 + rr) * 768) + 256 + h * 32 + cb;
            const float* vp = kp + 256;
            float vv[16];
            #pragma unroll
            for (int i = 0; i < 16; i += 4) {
                float4 kv = *(const float4*)(kp + i);
                Ks[rr * PAD + cb + i + 0] = kv.x;
                Ks[rr * PAD + cb + i + 1] = kv.y;
                Ks[rr * PAD + cb + i + 2] = kv.z;
                Ks[rr * PAD + cb + i + 3] = kv.w;
                float4 vq = *(const float4*)(vp + i);
                vv[i + 0] = vq.x; vv[i + 1] = vq.y; vv[i + 2] = vq.z; vv[i + 3] = vq.w;
            }
            #pragma unroll
            for (int ii = 0; ii < 16; ii++) {
                int i = (ii + par) & 15;
                Vt[(cb + i) * PADJ + rr] = vv[i];
            }
        }
        __syncthreads();

        float sc[16][4];
        #pragma unroll
        for (int nf = 0; nf < 16; nf++)
            #pragma unroll
            for (int q = 0; q < 4; q++) sc[nf][q] = 0.f;
        #pragma unroll
        for (int ks = 0; ks < 4; ks++) {
            const int kb = ks * 8;
            uint32_t afrag[4];
            afrag[0] = __float_as_uint(Qs[(qm + gr) * PAD + kb + tc]);
            afrag[1] = __float_as_uint(Qs[(qm + gr + 8) * PAD + kb + tc]);
            afrag[2] = __float_as_uint(Qs[(qm + gr) * PAD + kb + tc + 4]);
            afrag[3] = __float_as_uint(Qs[(qm + gr + 8) * PAD + kb + tc + 4]);
            #pragma unroll
            for (int nf = 0; nf < 16; nf++) {
                uint32_t bfrag[2];
                bfrag[0] = __float_as_uint(Ks[(nf * 8 + gr) * PAD + kb + tc]);
                bfrag[1] = __float_as_uint(Ks[(nf * 8 + gr) * PAD + kb + tc + 4]);
                MMA_TF32(sc[nf], afrag, bfrag);
            }
        }

        float tm0 = -1e30f, tm1 = -1e30f;
        #pragma unroll
        for (int nf = 0; nf < 16; nf++) {
            tm0 = fmaxf(tm0, fmaxf(sc[nf][0], sc[nf][1]));
            tm1 = fmaxf(tm1, fmaxf(sc[nf][2], sc[nf][3]));
        }
        tm0 = fmaxf(tm0, __shfl_xor_sync(0xffffffffu, tm0, 1));
        tm0 = fmaxf(tm0, __shfl_xor_sync(0xffffffffu, tm0, 2));
        tm1 = fmaxf(tm1, __shfl_xor_sync(0xffffffffu, tm1, 1));
        tm1 = fmaxf(tm1, __shfl_xor_sync(0xffffffffu, tm1, 2));
        float mn0 = fmaxf(m0, tm0), mn1 = fmaxf(m1, tm1);
        float corr0 = __expf(m0 - mn0), corr1 = __expf(m1 - mn1);
        m0 = mn0; m1 = mn1;
        float ls0 = 0.f, ls1 = 0.f;
        #pragma unroll
        for (int nf = 0; nf < 16; nf++) {
            float p0 = __expf(sc[nf][0] - mn0);
            float p1 = __expf(sc[nf][1] - mn0);
            float p2 = __expf(sc[nf][2] - mn1);
            float p3 = __expf(sc[nf][3] - mn1);
            ls0 += p0 + p1; ls1 += p2 + p3;
            *(float2*)(Ps + (qm + gr) * PADP + nf * 8 + 2 * tc)     = make_float2(p0, p1);
            *(float2*)(Ps + (qm + gr + 8) * PADP + nf * 8 + 2 * tc) = make_float2(p2, p3);
        }
        ls0 += __shfl_xor_sync(0xffffffffu, ls0, 1);
        ls0 += __shfl_xor_sync(0xffffffffu, ls0, 2);
        ls1 += __shfl_xor_sync(0xffffffffu, ls1, 1);
        ls1 += __shfl_xor_sync(0xffffffffu, ls1, 2);
        l0 = l0 * corr0 + ls0;
        l1 = l1 * corr1 + ls1;
        #pragma unroll
        for (int nf = 0; nf < 4; nf++) {
            oa[nf][0] *= corr0; oa[nf][1] *= corr0;
            oa[nf][2] *= corr1; oa[nf][3] *= corr1;
        }
        __syncwarp();

        #pragma unroll
        for (int ksj = 0; ksj < 16; ksj++) {
            const int j = ksj * 8;
            uint32_t afrag[4];
            afrag[0] = __float_as_uint(Ps[(qm + gr) * PADP + j + tc]);
            afrag[1] = __float_as_uint(Ps[(qm + gr + 8) * PADP + j + tc]);
            afrag[2] = __float_as_uint(Ps[(qm + gr) * PADP + j + tc + 4]);
            afrag[3] = __float_as_uint(Ps[(qm + gr + 8) * PADP + j + tc + 4]);
            #pragma unroll
            for (int nf = 0; nf < 4; nf++) {
                uint32_t bfrag[2];
                bfrag[0] = __float_as_uint(Vt[(nf * 8 + gr) * PADJ + j + tc]);
                bfrag[1] = __float_as_uint(Vt[(nf * 8 + gr) * PADJ + j + tc + 4]);
                MMA_TF32(oa[nf], afrag, bfrag);
            }
        }
    }

    const float inv0 = 1.0f / l0, inv1 = 1.0f / l1;
    const int r0 = q0 + qm + gr, r1 = r0 + 8;
    float* ob = o + (size_t)(b * NN) * 256 + h * 32;
    #pragma unroll
    for (int nf = 0; nf < 4; nf++) {
        const int d = nf * 8 + 2 * tc;
        *(float2*)(ob + (size_t)r0 * 256 + d) = make_float2(oa[nf][0] * inv0, oa[nf][1] * inv0);
        *(float2*)(ob + (size_t)r1 * 256 + d) = make_float2(oa[nf][2] * inv1, oa[nf][3] * inv1);
    }
}

// ================================ launch ====================================
extern "C" void kernel_launch(void* const* d_in, const int* in_sizes, int n_in,
                              void* d_out, int out_size)
{
    const float* x     = (const float*)d_in[0];
    const float* g1    = (const float*)d_in[2];
    const float* b1    = (const float*)d_in[3];
    const float* Wqkv  = (const float*)d_in[4];
    const float* Wproj = (const float*)d_in[5];
    const float* bproj = (const float*)d_in[6];
    const float* g2    = (const float*)d_in[7];
    const float* b2    = (const float*)d_in[8];
    const float* W1    = (const float*)d_in[9];
    const float* bb1   = (const float*)d_in[10];
    const float* W2    = (const float*)d_in[11];
    const float* bb2   = (const float*)d_in[12];
    float* out = (float*)d_out;

    float *p_h, *p_qkv, *p_o, *p_xn;
    __nv_bfloat16 *p_hb, *p_h2b, *p_midb, *p_Wqb, *p_W1b, *p_W2b;
    cudaGetSymbolAddress((void**)&p_h,    g_h);
    cudaGetSymbolAddress((void**)&p_qkv,  g_qkv);
    cudaGetSymbolAddress((void**)&p_o,    g_o);
    cudaGetSymbolAddress((void**)&p_xn,   g_xn);
    cudaGetSymbolAddress((void**)&p_hb,   g_hb);
    cudaGetSymbolAddress((void**)&p_h2b,  g_h2b);
    cudaGetSymbolAddress((void**)&p_midb, g_midb);
    cudaGetSymbolAddress((void**)&p_Wqb,  g_Wqkvb);
    cudaGetSymbolAddress((void**)&p_W1b,  g_W1b);
    cudaGetSymbolAddress((void**)&p_W2b,  g_W2b);

    cudaFuncSetAttribute(gemm_mma<false>, cudaFuncAttributeMaxDynamicSharedMemorySize, GEMM_DYN_BYTES);
    cudaFuncSetAttribute(gemm_bf16<false, false>, cudaFuncAttributeMaxDynamicSharedMemorySize, GEMM_BF_BYTES);
    cudaFuncSetAttribute(gemm_bf16<true, true>,   cudaFuncAttributeMaxDynamicSharedMemorySize, GEMM_BF_BYTES);
    cudaFuncSetAttribute(attn_kernel, cudaFuncAttributeMaxDynamicSharedMemorySize, ATTN_DYN_BYTES);

    // 0) weights -> bf16
    cvt_weights<<<1024, 256>>>(Wqkv, W1, W2, p_Wqb, p_W1b, p_W2b);

    // 1) h = LN1(x)  (fp32 for residual + bf16 for qkv GEMM)
    ln_kernel<true><<<MROWS / 8, 256>>>(x, g1, b1, p_h, p_hb);

    // 2) qkv = h @ Wqkv^T  (bf16 inputs, fp32 out)
    gemm_bf16<false, false><<<dim3(768 / 128, MROWS / 128), 256, GEMM_BF_BYTES>>>(
        p_hb, p_Wqb, nullptr, nullptr, p_qkv, MROWS, 3 * INF_, DD);

    // 3) attention -> o  (fp32)
    attn_kernel<<<dim3(NN / 128, BB * HH), 256, ATTN_DYN_BYTES>>>(p_qkv, p_o);

    // 4) xn = x + (o @ Wproj^T + bproj + h)  (tf32 GEMM)
    gemm_mma<false><<<dim3(INF_ / 128, MROWS / 128), 256, GEMM_DYN_BYTES>>>(
        p_o, Wproj, bproj, p_h, x, p_xn, MROWS, INF_, INF_);

    // 5) h2 = LN2(xn)  (bf16 only)
    ln_kernel<false><<<MROWS / 8, 256>>>(p_xn, g2, b2, nullptr, p_h2b);

    // 6) mid = gelu(h2 @ W1^T + bb1)  (bf16 in, bf16 out)
    gemm_bf16<true, true><<<dim3(HID / 128, MROWS / 128), 256, GEMM_BF_BYTES>>>(
        p_h2b, p_W1b, bb1, nullptr, p_midb, MROWS, HID, DD);

    // 7) out = xn + mid @ W2^T + bb2  (bf16 in, fp32 out + residual)
    gemm_bf16<false, false><<<dim3(DD / 128, MROWS / 128), 256, GEMM_BF_BYTES>>>(
        p_midb, p_W2b, bb2, p_xn, out, MROWS, DD, HID);
}